// round 12
// baseline (speedup 1.0000x reference)
#include <cuda_runtime.h>
#include <cuda_fp16.h>
#include <cstdint>

#define SEQ 1024
#define NB 4
#define NH 16
#define HD 64
#define EMB 1024

// scratch: fp16 copies of k/v/W, fp16 attention output, packed mask, queue
__device__ __align__(16) __half g_kh[NB * SEQ * EMB];
__device__ __align__(16) __half g_vh[NB * SEQ * EMB];
__device__ __align__(16) __half g_wh[EMB * EMB];
__device__ __align__(16) __half g_xh[NB * SEQ * EMB];
__device__ __align__(16) unsigned g_mpack[NB * SEQ * (SEQ / 32)];
__device__ unsigned g_xready[32];  // per (b,qt) row-block: 16 head tiles done
__device__ unsigned g_work;        // dynamic work-queue counter

__device__ __forceinline__ unsigned h2(float lo, float hi) {
    __half2 h = __floats2half2_rn(lo, hi);
    return *reinterpret_cast<unsigned*>(&h);
}

__device__ __forceinline__ float ex2(float x) {
    float r;
    asm("ex2.approx.ftz.f32 %0, %1;" : "=f"(r) : "f"(x));
    return r;
}

__device__ __forceinline__ void mma_f16(float* d, const unsigned* a, const unsigned* b) {
    asm volatile(
        "mma.sync.aligned.m16n8k16.row.col.f32.f16.f16.f32 "
        "{%0,%1,%2,%3}, {%4,%5,%6,%7}, {%8,%9}, {%0,%1,%2,%3};\n"
        : "+f"(d[0]), "+f"(d[1]), "+f"(d[2]), "+f"(d[3])
        : "r"(a[0]), "r"(a[1]), "r"(a[2]), "r"(a[3]), "r"(b[0]), "r"(b[1]));
}

__device__ __forceinline__ uint32_t smem_u32(const void* p) {
    uint32_t a;
    asm("{ .reg .u64 t; cvta.to.shared.u64 t, %1; cvt.u32.u64 %0, t; }" : "=r"(a) : "l"(p));
    return a;
}

__device__ __forceinline__ void ldsm4(unsigned* r, uint32_t a) {
    asm volatile("ldmatrix.sync.aligned.m8n8.x4.shared.b16 {%0,%1,%2,%3}, [%4];"
                 : "=r"(r[0]), "=r"(r[1]), "=r"(r[2]), "=r"(r[3]) : "r"(a));
}

__device__ __forceinline__ void ldsm4t(unsigned* r, uint32_t a) {
    asm volatile("ldmatrix.sync.aligned.m8n8.x4.trans.shared.b16 {%0,%1,%2,%3}, [%4];"
                 : "=r"(r[0]), "=r"(r[1]), "=r"(r[2]), "=r"(r[3]) : "r"(a));
}

__device__ __forceinline__ void cpa16(uint32_t dst, const void* src) {
    asm volatile("cp.async.cg.shared.global [%0], [%1], 16;" ::"r"(dst), "l"(src) : "memory");
}
__device__ __forceinline__ void cp_commit() {
    asm volatile("cp.async.commit_group;" ::: "memory");
}
__device__ __forceinline__ void cp_wait0() {
    asm volatile("cp.async.wait_group 0;" ::: "memory");
}
__device__ __forceinline__ void cp_wait1() {
    asm volatile("cp.async.wait_group 1;" ::: "memory");
}

// ---------------------------------------------------------------------------
// Kernel 1: preamble (R9 proven form) — fp32->fp16 of k/v/W + mask + resets
// blocks: 0..1023 k, 1024..2047 v, 2048..2303 W, 2304..2815 mask
// ---------------------------------------------------------------------------
__global__ __launch_bounds__(256) void pre_kernel(
    const float* __restrict__ k, const float* __restrict__ v,
    const float* __restrict__ W, const int* __restrict__ mask) {
    const int bid = blockIdx.x, tid = threadIdx.x;
    if (bid == 0) {
        if (tid < 32) g_xready[tid] = 0;
        if (tid == 32) g_work = 0;
    }
    if (bid < 2304) {
        const float* src;
        __half* dst;
        int off;
        if (bid < 1024)      { src = k; dst = g_kh; off = bid; }
        else if (bid < 2048) { src = v; dst = g_vh; off = bid - 1024; }
        else                 { src = W; dst = g_wh; off = bid - 2048; }
        const float4* s4 = reinterpret_cast<const float4*>(src) + (size_t)off * 1024;
        uint4* d16 = reinterpret_cast<uint4*>(dst) + (size_t)off * 512;
#pragma unroll
        for (int t = 0; t < 2; t++) {
            int i = tid + t * 256;
            float4 a = s4[2 * i];
            float4 b = s4[2 * i + 1];
            uint4 o;
            o.x = h2(a.x, a.y); o.y = h2(a.z, a.w);
            o.z = h2(b.x, b.y); o.w = h2(b.z, b.w);
            d16[i] = o;
        }
    } else {
        int word = (bid - 2304) * 256 + tid;
        const int4* m4 = reinterpret_cast<const int4*>(mask) + (size_t)word * 8;
        unsigned bits = 0;
#pragma unroll
        for (int i = 0; i < 8; i++) {
            int4 mv = m4[i];
            bits |= (mv.x != 0 ? 1u : 0u) << (i * 4 + 0);
            bits |= (mv.y != 0 ? 1u : 0u) << (i * 4 + 1);
            bits |= (mv.z != 0 ? 1u : 0u) << (i * 4 + 2);
            bits |= (mv.w != 0 ? 1u : 0u) << (i * 4 + 3);
        }
        g_mpack[word] = bits;
    }
}

// ---------------------------------------------------------------------------
// Kernel 2: persistent worker. Work queue: items 0..511 attention tiles
// (rb-major: item = rb*16 + head), 512..767 projection tiles (rb-major).
// 296 persistent CTAs pop via atomicAdd; queue order => all attn grabbed
// before any proj => spin only possible at the extreme tail.
// ---------------------------------------------------------------------------
#define ATTN_STG 18432
#define PROJ_AST 18432
#define MAIN_SMEM (6 * PROJ_AST)  // 110592 (proj needs it; attn uses 55296)

__device__ __forceinline__ void attn_body(
    int item, const float* __restrict__ q, char* dynsm, uint32_t smb,
    int tid, int w, int lane, int g, int j, int lr, int grp) {
    const int h = item & 15;
    const int rb = item >> 4;
    const int qt = rb & 7;
    const int b = rb >> 3;
    const int q0 = qt * 128;

    const float* qb = q + ((size_t)b * SEQ + q0) * EMB + h * HD;
    const __half* kbp = g_kh + (size_t)b * SEQ * EMB + h * HD;
    const __half* vbp = g_vh + (size_t)b * SEQ * EMB + h * HD;

    const float C = 0.125f * 1.44269504f;

    // stage Q (128x64) fp32 -> fp16 into stage0 directly
#pragma unroll
    for (int t = 0; t < 8; t++) {
        int idx = tid + t * 256;
        int row = idx >> 4, c4 = idx & 15;
        float4 val = *reinterpret_cast<const float4*>(qb + (size_t)row * EMB + c4 * 4);
        *reinterpret_cast<uint2*>(dynsm + row * 144 + c4 * 8) =
            make_uint2(h2(val.x, val.y), h2(val.z, val.w));
    }
    __syncthreads();

    unsigned qa[4][4];
#pragma unroll
    for (int kk = 0; kk < 4; kk++) {
        uint32_t addr = smb + (w * 16 + lr + 8 * (grp & 1)) * 144 +
                        kk * 32 + (grp >> 1) * 16;
        ldsm4(qa[kk], addr);
    }
    __syncthreads();

    auto issueKV = [&](int kn, uint32_t st) {
#pragma unroll
        for (int t = 0; t < 2; t++) {
            int c = tid + t * 256;
            int row = c >> 3, col = c & 7;
            cpa16(st + row * 144 + col * 16,
                  kbp + (size_t)(kn * 64 + row) * EMB + col * 8);
            cpa16(st + (64 + row) * 144 + col * 16,
                  vbp + (size_t)(kn * 64 + row) * EMB + col * 8);
        }
        cp_commit();
    };

    issueKV(0, smb);
    issueKV(1, smb + ATTN_STG);

    float oacc[8][4];
#pragma unroll
    for (int n = 0; n < 8; n++)
#pragma unroll
        for (int i = 0; i < 4; i++) oacc[n][i] = 0.f;

    float lp0 = 0.f, lp1 = 0.f;

    const unsigned* mp0 = g_mpack + ((size_t)b * SEQ + q0 + w * 16 + g) * 32;
    const unsigned* mp1 = mp0 + 8 * 32;

    int c3 = 0, i3 = 2;
    for (int kb = 0; kb < 16; kb++) {
        const uint32_t st = smb + c3 * ATTN_STG;
        if (kb < 15) cp_wait1(); else cp_wait0();
        __syncthreads();

        float sacc[8][4];
#pragma unroll
        for (int n = 0; n < 8; n++) {
            sacc[n][0] = sacc[n][1] = sacc[n][2] = sacc[n][3] = 0.f;
            unsigned bk[8];
            uint32_t rbad = st + (n * 8 + lr) * 144 + grp * 16;
            ldsm4(bk, rbad);
            ldsm4(bk + 4, rbad + 64);
#pragma unroll
            for (int kk = 0; kk < 4; kk++) mma_f16(sacc[n], qa[kk], &bk[2 * kk]);
        }

        uint2 w0 = *reinterpret_cast<const uint2*>(mp0 + 2 * kb);
        uint2 w1 = *reinterpret_cast<const uint2*>(mp1 + 2 * kb);
        unsigned long long mm0 = (unsigned long long)w0.x | ((unsigned long long)w0.y << 32);
        unsigned long long mm1 = (unsigned long long)w1.x | ((unsigned long long)w1.y << 32);

#pragma unroll
        for (int n = 0; n < 8; n++) {
            int p = n * 8 + 2 * j;
            float e0 = ((mm0 >> p) & 1) ? ex2(sacc[n][0] * C) : 0.f;
            float e1 = ((mm0 >> (p + 1)) & 1) ? ex2(sacc[n][1] * C) : 0.f;
            float e2 = ((mm1 >> p) & 1) ? ex2(sacc[n][2] * C) : 0.f;
            float e3 = ((mm1 >> (p + 1)) & 1) ? ex2(sacc[n][3] * C) : 0.f;
            sacc[n][0] = e0; sacc[n][1] = e1; sacc[n][2] = e2; sacc[n][3] = e3;
            lp0 += e0 + e1;
            lp1 += e2 + e3;
        }

#pragma unroll
        for (int t = 0; t < 4; t++) {
            unsigned pa[4];
            pa[0] = h2(sacc[2 * t][0], sacc[2 * t][1]);
            pa[1] = h2(sacc[2 * t][2], sacc[2 * t][3]);
            pa[2] = h2(sacc[2 * t + 1][0], sacc[2 * t + 1][1]);
            pa[3] = h2(sacc[2 * t + 1][2], sacc[2 * t + 1][3]);
#pragma unroll
            for (int ndp = 0; ndp < 4; ndp++) {
                unsigned bv[4];
                uint32_t addr = st + (64 + 16 * t + lr + 8 * (grp & 1)) * 144 +
                                ndp * 32 + (grp >> 1) * 16;
                ldsm4t(bv, addr);
                mma_f16(oacc[2 * ndp], pa, bv);
                mma_f16(oacc[2 * ndp + 1], pa, bv + 2);
            }
        }

        if (kb + 2 < 16) issueKV(kb + 2, smb + i3 * ATTN_STG);

        c3 = (c3 == 2) ? 0 : c3 + 1;
        i3 = (i3 == 2) ? 0 : i3 + 1;
    }

    lp0 += __shfl_xor_sync(0xffffffffu, lp0, 1);
    lp0 += __shfl_xor_sync(0xffffffffu, lp0, 2);
    lp1 += __shfl_xor_sync(0xffffffffu, lp1, 1);
    lp1 += __shfl_xor_sync(0xffffffffu, lp1, 2);

    float inv0 = 1.f / lp0, inv1 = 1.f / lp1;
    __half* obase = g_xh + ((size_t)b * SEQ + q0 + w * 16 + g) * EMB + h * HD;
#pragma unroll
    for (int nd = 0; nd < 8; nd++) {
        int col = nd * 8 + 2 * j;
        *reinterpret_cast<unsigned*>(obase + col) =
            h2(oacc[nd][0] * inv0, oacc[nd][1] * inv0);
        *reinterpret_cast<unsigned*>(obase + (size_t)8 * EMB + col) =
            h2(oacc[nd][2] * inv1, oacc[nd][3] * inv1);
    }

    // release: fence stores, then one thread signals this head tile done
    __threadfence();
    __syncthreads();
    if (tid == 0) atomicAdd(&g_xready[rb], 1u);
}

__device__ __forceinline__ void proj_body(
    int pid, const float* __restrict__ bias, float* __restrict__ out,
    uint32_t smb, int tid, int w, int lane, int g, int j, int lr, int grp) {
    const int rb = pid >> 3;
    const int bm = rb * 128;
    const int bn = (pid & 7) * 128;

    // acquire: all 16 head tiles of this row-block must be complete
    if (tid == 0) {
        while (*(volatile unsigned*)&g_xready[rb] != 16u) __nanosleep(100);
    }
    __syncthreads();
    __threadfence();

    const int wm = (w >> 2) * 64;
    const int wn = (w & 3) * 32;

    const __half* xb = g_xh + (size_t)bm * EMB;
    const __half* wb = g_wh + (size_t)bn * EMB;

    auto issue = [&](int kb, int stg) {
        uint32_t au = smb + stg * PROJ_AST;
        uint32_t bu = smb + 3 * PROJ_AST + stg * PROJ_AST;
#pragma unroll
        for (int t = 0; t < 4; t++) {
            int c = tid + t * 256;
            int row = c >> 3, col = c & 7;
            cpa16(au + row * 144 + col * 16,
                  xb + (size_t)row * EMB + kb * 64 + col * 8);
            cpa16(bu + row * 144 + col * 16,
                  wb + (size_t)row * EMB + kb * 64 + col * 8);
        }
        cp_commit();
    };

    issue(0, 0);
    issue(1, 1);

    float acc[4][4][4];
#pragma unroll
    for (int mi = 0; mi < 4; mi++)
#pragma unroll
        for (int ni = 0; ni < 4; ni++)
#pragma unroll
            for (int i = 0; i < 4; i++) acc[mi][ni][i] = 0.f;

    int c3 = 0, i3 = 2;
    for (int kb = 0; kb < 16; kb++) {
        const uint32_t au = smb + c3 * PROJ_AST;
        const uint32_t bu = smb + 3 * PROJ_AST + c3 * PROJ_AST;
        if (kb < 15) cp_wait1(); else cp_wait0();
        __syncthreads();

#pragma unroll
        for (int half = 0; half < 2; half++) {
            const int cb = half * 64;
            unsigned af[4][2][4];
#pragma unroll
            for (int mi = 0; mi < 4; mi++)
#pragma unroll
                for (int kk = 0; kk < 2; kk++) {
                    uint32_t addr = au + (wm + mi * 16 + lr + 8 * (grp & 1)) * 144 +
                                    cb + kk * 32 + (grp >> 1) * 16;
                    ldsm4(af[mi][kk], addr);
                }
#pragma unroll
            for (int ni = 0; ni < 4; ni++) {
                unsigned bf[4];
                uint32_t addr = bu + (wn + ni * 8 + lr) * 144 + cb + grp * 16;
                ldsm4(bf, addr);
#pragma unroll
                for (int mi = 0; mi < 4; mi++) {
                    mma_f16(acc[mi][ni], af[mi][0], bf);
                    mma_f16(acc[mi][ni], af[mi][1], bf + 2);
                }
            }
        }

        if (kb + 2 < 16) issue(kb + 2, i3);

        c3 = (c3 == 2) ? 0 : c3 + 1;
        i3 = (i3 == 2) ? 0 : i3 + 1;
    }

#pragma unroll
    for (int mi = 0; mi < 4; mi++) {
        int r = bm + wm + mi * 16 + g;
#pragma unroll
        for (int ni = 0; ni < 4; ni++) {
            int col = bn + wn + ni * 8 + 2 * j;
            float2 bb = *reinterpret_cast<const float2*>(bias + col);
            *reinterpret_cast<float2*>(out + (size_t)r * EMB + col) =
                make_float2(acc[mi][ni][0] + bb.x, acc[mi][ni][1] + bb.y);
            *reinterpret_cast<float2*>(out + (size_t)(r + 8) * EMB + col) =
                make_float2(acc[mi][ni][2] + bb.x, acc[mi][ni][3] + bb.y);
        }
    }
}

__global__ __launch_bounds__(256, 2) void main_kernel(
    const float* __restrict__ q, const float* __restrict__ bias,
    float* __restrict__ out) {
    extern __shared__ __align__(16) char dynsm[];
    __shared__ unsigned s_item;
    const uint32_t smb = smem_u32(dynsm);

    const int tid = threadIdx.x;
    const int w = tid >> 5;
    const int lane = tid & 31;
    const int g = lane >> 2;
    const int j = lane & 3;
    const int lr = lane & 7;
    const int grp = lane >> 3;

    for (;;) {
        if (tid == 0) s_item = atomicAdd(&g_work, 1u);
        __syncthreads();  // also guards smem reuse from previous item
        const unsigned item = s_item;
        if (item >= 768u) return;

        if (item < 512u)
            attn_body((int)item, q, dynsm, smb, tid, w, lane, g, j, lr, grp);
        else
            proj_body((int)item - 512, bias, out, smb, tid, w, lane, g, j, lr, grp);
        __syncthreads();  // all warps done with this item's smem
    }
}

// ---------------------------------------------------------------------------
extern "C" void kernel_launch(void* const* d_in, const int* in_sizes, int n_in,
                              void* d_out, int out_size) {
    const float* q = (const float*)d_in[0];
    const float* k = (const float*)d_in[1];
    const float* v = (const float*)d_in[2];
    const int* mask = (const int*)d_in[3];
    const float* Wm = (const float*)d_in[4];
    const float* bias = (const float*)d_in[5];
    float* out = (float*)d_out;

    static bool attr_done = false;
    if (!attr_done) {
        cudaFuncSetAttribute(main_kernel, cudaFuncAttributeMaxDynamicSharedMemorySize,
                             MAIN_SMEM);
        attr_done = true;
    }

    pre_kernel<<<2816, 256>>>(k, v, Wm, mask);
    main_kernel<<<296, 256, MAIN_SMEM>>>(q, bias, out);
}

// round 13
// speedup vs baseline: 1.0501x; 1.0501x over previous
#include <cuda_runtime.h>
#include <cuda_fp16.h>
#include <cstdint>

#define SEQ 1024
#define NB 4
#define NH 16
#define HD 64
#define EMB 1024

// scratch: fp16 copies of k/v/W, fp16 attention output, packed mask
__device__ __align__(16) __half g_kh[NB * SEQ * EMB];
__device__ __align__(16) __half g_vh[NB * SEQ * EMB];
__device__ __align__(16) __half g_wh[EMB * EMB];
__device__ __align__(16) __half g_xh[NB * SEQ * EMB];
__device__ __align__(16) unsigned g_mpack[NB * SEQ * (SEQ / 32)];

__device__ __forceinline__ unsigned h2(float lo, float hi) {
    __half2 h = __floats2half2_rn(lo, hi);
    return *reinterpret_cast<unsigned*>(&h);
}

__device__ __forceinline__ float ex2(float x) {
    float r;
    asm("ex2.approx.ftz.f32 %0, %1;" : "=f"(r) : "f"(x));
    return r;
}

__device__ __forceinline__ void mma_f16(float* d, const unsigned* a, const unsigned* b) {
    asm volatile(
        "mma.sync.aligned.m16n8k16.row.col.f32.f16.f16.f32 "
        "{%0,%1,%2,%3}, {%4,%5,%6,%7}, {%8,%9}, {%0,%1,%2,%3};\n"
        : "+f"(d[0]), "+f"(d[1]), "+f"(d[2]), "+f"(d[3])
        : "r"(a[0]), "r"(a[1]), "r"(a[2]), "r"(a[3]), "r"(b[0]), "r"(b[1]));
}

__device__ __forceinline__ uint32_t smem_u32(const void* p) {
    uint32_t a;
    asm("{ .reg .u64 t; cvta.to.shared.u64 t, %1; cvt.u32.u64 %0, t; }" : "=r"(a) : "l"(p));
    return a;
}

__device__ __forceinline__ void ldsm4(unsigned* r, uint32_t a) {
    asm volatile("ldmatrix.sync.aligned.m8n8.x4.shared.b16 {%0,%1,%2,%3}, [%4];"
                 : "=r"(r[0]), "=r"(r[1]), "=r"(r[2]), "=r"(r[3]) : "r"(a));
}

__device__ __forceinline__ void ldsm4t(unsigned* r, uint32_t a) {
    asm volatile("ldmatrix.sync.aligned.m8n8.x4.trans.shared.b16 {%0,%1,%2,%3}, [%4];"
                 : "=r"(r[0]), "=r"(r[1]), "=r"(r[2]), "=r"(r[3]) : "r"(a));
}

__device__ __forceinline__ void cpa16(uint32_t dst, const void* src) {
    asm volatile("cp.async.cg.shared.global [%0], [%1], 16;" ::"r"(dst), "l"(src) : "memory");
}
__device__ __forceinline__ void cp_commit() {
    asm volatile("cp.async.commit_group;" ::: "memory");
}
__device__ __forceinline__ void cp_wait0() {
    asm volatile("cp.async.wait_group 0;" ::: "memory");
}
__device__ __forceinline__ void cp_wait1() {
    asm volatile("cp.async.wait_group 1;" ::: "memory");
}

// ---------------------------------------------------------------------------
// Kernel 1: preamble — fp32->fp16 of k/v + mask bitpack (W handled in attn)
// blocks: 0..1023 k, 1024..2047 v, 2048..2559 mask
// ---------------------------------------------------------------------------
__global__ __launch_bounds__(256) void pre_kernel(
    const float* __restrict__ k, const float* __restrict__ v,
    const int* __restrict__ mask) {
    const int bid = blockIdx.x, tid = threadIdx.x;
    if (bid < 2048) {
        const float* src;
        __half* dst;
        int off;
        if (bid < 1024) { src = k; dst = g_kh; off = bid; }
        else            { src = v; dst = g_vh; off = bid - 1024; }
        const float4* s4 = reinterpret_cast<const float4*>(src) + (size_t)off * 1024;
        uint4* d16 = reinterpret_cast<uint4*>(dst) + (size_t)off * 512;
#pragma unroll
        for (int t = 0; t < 2; t++) {
            int i = tid + t * 256;
            float4 a = s4[2 * i];
            float4 b = s4[2 * i + 1];
            uint4 o;
            o.x = h2(a.x, a.y); o.y = h2(a.z, a.w);
            o.z = h2(b.x, b.y); o.w = h2(b.z, b.w);
            d16[i] = o;
        }
    } else {
        int word = (bid - 2048) * 256 + tid;
        const int4* m4 = reinterpret_cast<const int4*>(mask) + (size_t)word * 8;
        unsigned bits = 0;
#pragma unroll
        for (int i = 0; i < 8; i++) {
            int4 mv = m4[i];
            bits |= (mv.x != 0 ? 1u : 0u) << (i * 4 + 0);
            bits |= (mv.y != 0 ? 1u : 0u) << (i * 4 + 1);
            bits |= (mv.z != 0 ? 1u : 0u) << (i * 4 + 2);
            bits |= (mv.w != 0 ? 1u : 0u) << (i * 4 + 3);
        }
        g_mpack[word] = bits;
    }
}

// ---------------------------------------------------------------------------
// Kernel 2: fused flash attention (R9 proven body) + 64 bonus W-convert blocks
// grid (9,16,4): x<8 -> attention tile; x==8 -> convert 16 rows of W.
// W-blocks ride in attention's partial second wave (512+64 = 576 <= 592 slots).
// ---------------------------------------------------------------------------
#define ATTN_STG 18432
#define ATTN_SMEM (3 * ATTN_STG)

__global__ __launch_bounds__(256, 2) void attn_kernel(
    const float* __restrict__ q, const float* __restrict__ W) {
    extern __shared__ __align__(16) char dynsm[];
    const uint32_t smb = smem_u32(dynsm);

    const int tid = threadIdx.x;

    if (blockIdx.x == 8) {
        // ---- bonus block: convert 16 rows of W (16384 floats) to fp16 ----
        const int off = blockIdx.z * 16 + blockIdx.y;  // 0..63
        const float4* s4 = reinterpret_cast<const float4*>(W) + (size_t)off * 4096;
        uint4* d16 = reinterpret_cast<uint4*>(g_wh) + (size_t)off * 2048;
#pragma unroll
        for (int t = 0; t < 8; t++) {
            int i = tid + t * 256;  // 0..2047
            float4 a = s4[2 * i];
            float4 b = s4[2 * i + 1];
            uint4 o;
            o.x = h2(a.x, a.y); o.y = h2(a.z, a.w);
            o.z = h2(b.x, b.y); o.w = h2(b.z, b.w);
            d16[i] = o;
        }
        return;
    }

    const int w = tid >> 5;
    const int lane = tid & 31;
    const int g = lane >> 2;
    const int j = lane & 3;
    const int lr = lane & 7;
    const int grp = lane >> 3;

    const int qt = blockIdx.x;
    const int h = blockIdx.y;
    const int b = blockIdx.z;
    const int q0 = qt * 128;

    const float* qb = q + ((size_t)b * SEQ + q0) * EMB + h * HD;
    const __half* kbp = g_kh + (size_t)b * SEQ * EMB + h * HD;
    const __half* vbp = g_vh + (size_t)b * SEQ * EMB + h * HD;

    const float C = 0.125f * 1.44269504f;

    // ---- stage Q (128x64) fp32 -> fp16 into stage0 directly ----
#pragma unroll
    for (int t = 0; t < 8; t++) {
        int idx = tid + t * 256;
        int row = idx >> 4, c4 = idx & 15;
        float4 val = *reinterpret_cast<const float4*>(qb + (size_t)row * EMB + c4 * 4);
        *reinterpret_cast<uint2*>(dynsm + row * 144 + c4 * 8) =
            make_uint2(h2(val.x, val.y), h2(val.z, val.w));
    }
    __syncthreads();

    unsigned qa[4][4];
#pragma unroll
    for (int kk = 0; kk < 4; kk++) {
        uint32_t addr = smb + (w * 16 + lr + 8 * (grp & 1)) * 144 +
                        kk * 32 + (grp >> 1) * 16;
        ldsm4(qa[kk], addr);
    }
    __syncthreads();

    auto issueKV = [&](int kn, uint32_t st) {
#pragma unroll
        for (int t = 0; t < 2; t++) {
            int c = tid + t * 256;
            int row = c >> 3, col = c & 7;
            cpa16(st + row * 144 + col * 16,
                  kbp + (size_t)(kn * 64 + row) * EMB + col * 8);
            cpa16(st + (64 + row) * 144 + col * 16,
                  vbp + (size_t)(kn * 64 + row) * EMB + col * 8);
        }
        cp_commit();
    };

    issueKV(0, smb);
    issueKV(1, smb + ATTN_STG);

    float oacc[8][4];
#pragma unroll
    for (int n = 0; n < 8; n++)
#pragma unroll
        for (int i = 0; i < 4; i++) oacc[n][i] = 0.f;

    float lp0 = 0.f, lp1 = 0.f;

    const unsigned* mp0 = g_mpack + ((size_t)b * SEQ + q0 + w * 16 + g) * 32;
    const unsigned* mp1 = mp0 + 8 * 32;

    int c3 = 0, i3 = 2;
    for (int kb = 0; kb < 16; kb++) {
        const uint32_t st = smb + c3 * ATTN_STG;
        if (kb < 15) cp_wait1(); else cp_wait0();
        __syncthreads();

        float sacc[8][4];
#pragma unroll
        for (int n = 0; n < 8; n++) {
            sacc[n][0] = sacc[n][1] = sacc[n][2] = sacc[n][3] = 0.f;
            unsigned bk[8];
            uint32_t rb = st + (n * 8 + lr) * 144 + grp * 16;
            ldsm4(bk, rb);
            ldsm4(bk + 4, rb + 64);
#pragma unroll
            for (int kk = 0; kk < 4; kk++) mma_f16(sacc[n], qa[kk], &bk[2 * kk]);
        }

        uint2 w0 = *reinterpret_cast<const uint2*>(mp0 + 2 * kb);
        uint2 w1 = *reinterpret_cast<const uint2*>(mp1 + 2 * kb);
        unsigned long long mm0 = (unsigned long long)w0.x | ((unsigned long long)w0.y << 32);
        unsigned long long mm1 = (unsigned long long)w1.x | ((unsigned long long)w1.y << 32);

#pragma unroll
        for (int n = 0; n < 8; n++) {
            int p = n * 8 + 2 * j;
            float e0 = ((mm0 >> p) & 1) ? ex2(sacc[n][0] * C) : 0.f;
            float e1 = ((mm0 >> (p + 1)) & 1) ? ex2(sacc[n][1] * C) : 0.f;
            float e2 = ((mm1 >> p) & 1) ? ex2(sacc[n][2] * C) : 0.f;
            float e3 = ((mm1 >> (p + 1)) & 1) ? ex2(sacc[n][3] * C) : 0.f;
            sacc[n][0] = e0; sacc[n][1] = e1; sacc[n][2] = e2; sacc[n][3] = e3;
            lp0 += e0 + e1;
            lp1 += e2 + e3;
        }

#pragma unroll
        for (int t = 0; t < 4; t++) {
            unsigned pa[4];
            pa[0] = h2(sacc[2 * t][0], sacc[2 * t][1]);
            pa[1] = h2(sacc[2 * t][2], sacc[2 * t][3]);
            pa[2] = h2(sacc[2 * t + 1][0], sacc[2 * t + 1][1]);
            pa[3] = h2(sacc[2 * t + 1][2], sacc[2 * t + 1][3]);
#pragma unroll
            for (int ndp = 0; ndp < 4; ndp++) {
                unsigned bv[4];
                uint32_t addr = st + (64 + 16 * t + lr + 8 * (grp & 1)) * 144 +
                                ndp * 32 + (grp >> 1) * 16;
                ldsm4t(bv, addr);
                mma_f16(oacc[2 * ndp], pa, bv);
                mma_f16(oacc[2 * ndp + 1], pa, bv + 2);
            }
        }

        if (kb + 2 < 16) issueKV(kb + 2, smb + i3 * ATTN_STG);

        c3 = (c3 == 2) ? 0 : c3 + 1;
        i3 = (i3 == 2) ? 0 : i3 + 1;
    }

    lp0 += __shfl_xor_sync(0xffffffffu, lp0, 1);
    lp0 += __shfl_xor_sync(0xffffffffu, lp0, 2);
    lp1 += __shfl_xor_sync(0xffffffffu, lp1, 1);
    lp1 += __shfl_xor_sync(0xffffffffu, lp1, 2);

    float inv0 = 1.f / lp0, inv1 = 1.f / lp1;
    __half* obase = g_xh + ((size_t)b * SEQ + q0 + w * 16 + g) * EMB + h * HD;
#pragma unroll
    for (int nd = 0; nd < 8; nd++) {
        int col = nd * 8 + 2 * j;
        *reinterpret_cast<unsigned*>(obase + col) =
            h2(oacc[nd][0] * inv0, oacc[nd][1] * inv0);
        *reinterpret_cast<unsigned*>(obase + (size_t)8 * EMB + col) =
            h2(oacc[nd][2] * inv1, oacc[nd][3] * inv1);
    }
}

// ---------------------------------------------------------------------------
// Kernel 3: out = X (4096x1024) @ W^T + b, fp16 mma + ldmatrix,
// K-chunk 64 per stage (2 reg sub-chunks), 3-stage cp.async, 1 barrier/iter.
// ---------------------------------------------------------------------------
#define PROJ_AST 18432
#define PROJ_SMEM (6 * PROJ_AST)

__global__ __launch_bounds__(256, 2) void proj_kernel(
    const float* __restrict__ bias, float* __restrict__ out) {
    extern __shared__ __align__(16) char dynsm[];
    const uint32_t smb = smem_u32(dynsm);

    const int tid = threadIdx.x;
    const int w = tid >> 5, lane = tid & 31, g = lane >> 2, j = lane & 3;
    const int lr = lane & 7, grp = lane >> 3;
    const int wm = (w >> 2) * 64;
    const int wn = (w & 3) * 32;
    const int bm = blockIdx.y * 128;
    const int bn = blockIdx.x * 128;

    const __half* xb = g_xh + (size_t)bm * EMB;
    const __half* wb = g_wh + (size_t)bn * EMB;

    auto issue = [&](int kb, int stg) {
        uint32_t au = smb + stg * PROJ_AST;
        uint32_t bu = smb + 3 * PROJ_AST + stg * PROJ_AST;
#pragma unroll
        for (int t = 0; t < 4; t++) {
            int c = tid + t * 256;
            int row = c >> 3, col = c & 7;
            cpa16(au + row * 144 + col * 16,
                  xb + (size_t)row * EMB + kb * 64 + col * 8);
            cpa16(bu + row * 144 + col * 16,
                  wb + (size_t)row * EMB + kb * 64 + col * 8);
        }
        cp_commit();
    };

    issue(0, 0);
    issue(1, 1);

    float acc[4][4][4];
#pragma unroll
    for (int mi = 0; mi < 4; mi++)
#pragma unroll
        for (int ni = 0; ni < 4; ni++)
#pragma unroll
            for (int i = 0; i < 4; i++) acc[mi][ni][i] = 0.f;

    int c3 = 0, i3 = 2;
    for (int kb = 0; kb < 16; kb++) {
        const uint32_t au = smb + c3 * PROJ_AST;
        const uint32_t bu = smb + 3 * PROJ_AST + c3 * PROJ_AST;
        if (kb < 15) cp_wait1(); else cp_wait0();
        __syncthreads();

#pragma unroll
        for (int half = 0; half < 2; half++) {
            const int cb = half * 64;
            unsigned af[4][2][4];
#pragma unroll
            for (int mi = 0; mi < 4; mi++)
#pragma unroll
                for (int kk = 0; kk < 2; kk++) {
                    uint32_t addr = au + (wm + mi * 16 + lr + 8 * (grp & 1)) * 144 +
                                    cb + kk * 32 + (grp >> 1) * 16;
                    ldsm4(af[mi][kk], addr);
                }
#pragma unroll
            for (int ni = 0; ni < 4; ni++) {
                unsigned bf[4];
                uint32_t addr = bu + (wn + ni * 8 + lr) * 144 + cb + grp * 16;
                ldsm4(bf, addr);
#pragma unroll
                for (int mi = 0; mi < 4; mi++) {
                    mma_f16(acc[mi][ni], af[mi][0], bf);
                    mma_f16(acc[mi][ni], af[mi][1], bf + 2);
                }
            }
        }

        if (kb + 2 < 16) issue(kb + 2, i3);

        c3 = (c3 == 2) ? 0 : c3 + 1;
        i3 = (i3 == 2) ? 0 : i3 + 1;
    }

#pragma unroll
    for (int mi = 0; mi < 4; mi++) {
        int r = bm + wm + mi * 16 + g;
#pragma unroll
        for (int ni = 0; ni < 4; ni++) {
            int col = bn + wn + ni * 8 + 2 * j;
            float2 bb = *reinterpret_cast<const float2*>(bias + col);
            *reinterpret_cast<float2*>(out + (size_t)r * EMB + col) =
                make_float2(acc[mi][ni][0] + bb.x, acc[mi][ni][1] + bb.y);
            *reinterpret_cast<float2*>(out + (size_t)(r + 8) * EMB + col) =
                make_float2(acc[mi][ni][2] + bb.x, acc[mi][ni][3] + bb.y);
        }
    }
}

// ---------------------------------------------------------------------------
extern "C" void kernel_launch(void* const* d_in, const int* in_sizes, int n_in,
                              void* d_out, int out_size) {
    const float* q = (const float*)d_in[0];
    const float* k = (const float*)d_in[1];
    const float* v = (const float*)d_in[2];
    const int* mask = (const int*)d_in[3];
    const float* Wm = (const float*)d_in[4];
    const float* bias = (const float*)d_in[5];
    float* out = (float*)d_out;

    static bool attr_done = false;
    if (!attr_done) {
        cudaFuncSetAttribute(attn_kernel, cudaFuncAttributeMaxDynamicSharedMemorySize,
                             ATTN_SMEM);
        cudaFuncSetAttribute(proj_kernel, cudaFuncAttributeMaxDynamicSharedMemorySize,
                             PROJ_SMEM);
        attr_done = true;
    }

    pre_kernel<<<2560, 256>>>(k, v, mask);

    dim3 ga(9, NH, NB);  // x==8 lane converts W
    attn_kernel<<<ga, 256, ATTN_SMEM>>>(q, Wm);

    dim3 gp(8, 32);
    proj_kernel<<<gp, 256, PROJ_SMEM>>>(bias, out);
}

// round 14
// speedup vs baseline: 1.0524x; 1.0022x over previous
#include <cuda_runtime.h>
#include <cuda_fp16.h>
#include <cstdint>

#define SEQ 1024
#define NB 4
#define NH 16
#define HD 64
#define EMB 1024

// scratch: fp16 copies of k/v/W, fp16 attention output, packed mask
__device__ __align__(16) __half g_kh[NB * SEQ * EMB];
__device__ __align__(16) __half g_vh[NB * SEQ * EMB];
__device__ __align__(16) __half g_wh[EMB * EMB];
__device__ __align__(16) __half g_xh[NB * SEQ * EMB];
__device__ __align__(16) unsigned g_mpack[NB * SEQ * (SEQ / 32)];

__device__ __forceinline__ unsigned h2(float lo, float hi) {
    __half2 h = __floats2half2_rn(lo, hi);
    return *reinterpret_cast<unsigned*>(&h);
}

__device__ __forceinline__ float ex2(float x) {
    float r;
    asm("ex2.approx.ftz.f32 %0, %1;" : "=f"(r) : "f"(x));
    return r;
}

__device__ __forceinline__ void mma_f16(float* d, const unsigned* a, const unsigned* b) {
    asm volatile(
        "mma.sync.aligned.m16n8k16.row.col.f32.f16.f16.f32 "
        "{%0,%1,%2,%3}, {%4,%5,%6,%7}, {%8,%9}, {%0,%1,%2,%3};\n"
        : "+f"(d[0]), "+f"(d[1]), "+f"(d[2]), "+f"(d[3])
        : "r"(a[0]), "r"(a[1]), "r"(a[2]), "r"(a[3]), "r"(b[0]), "r"(b[1]));
}

__device__ __forceinline__ uint32_t smem_u32(const void* p) {
    uint32_t a;
    asm("{ .reg .u64 t; cvta.to.shared.u64 t, %1; cvt.u32.u64 %0, t; }" : "=r"(a) : "l"(p));
    return a;
}

__device__ __forceinline__ void ldsm4(unsigned* r, uint32_t a) {
    asm volatile("ldmatrix.sync.aligned.m8n8.x4.shared.b16 {%0,%1,%2,%3}, [%4];"
                 : "=r"(r[0]), "=r"(r[1]), "=r"(r[2]), "=r"(r[3]) : "r"(a));
}

__device__ __forceinline__ void ldsm4t(unsigned* r, uint32_t a) {
    asm volatile("ldmatrix.sync.aligned.m8n8.x4.trans.shared.b16 {%0,%1,%2,%3}, [%4];"
                 : "=r"(r[0]), "=r"(r[1]), "=r"(r[2]), "=r"(r[3]) : "r"(a));
}

__device__ __forceinline__ void cpa16(uint32_t dst, const void* src) {
    asm volatile("cp.async.cg.shared.global [%0], [%1], 16;" ::"r"(dst), "l"(src) : "memory");
}
__device__ __forceinline__ void cp_commit() {
    asm volatile("cp.async.commit_group;" ::: "memory");
}
__device__ __forceinline__ void cp_wait0() {
    asm volatile("cp.async.wait_group 0;" ::: "memory");
}
__device__ __forceinline__ void cp_wait1() {
    asm volatile("cp.async.wait_group 1;" ::: "memory");
}

// ---------------------------------------------------------------------------
// Kernel 1: preamble — fp32->fp16 of k/v (thin blocks for max concurrency)
// + mask bitpack. blocks: 0..2047 k, 2048..4095 v, 4096..4607 mask.
// Thin block = 2048 floats; thread = 2 LDG.128 -> 1 STG.128.
// ---------------------------------------------------------------------------
__global__ __launch_bounds__(256) void pre_kernel(
    const float* __restrict__ k, const float* __restrict__ v,
    const int* __restrict__ mask) {
    const int bid = blockIdx.x, tid = threadIdx.x;
    if (bid < 4096) {
        const float* src;
        __half* dst;
        int off;
        if (bid < 2048) { src = k; dst = g_kh; off = bid; }
        else            { src = v; dst = g_vh; off = bid - 2048; }
        const float4* s4 = reinterpret_cast<const float4*>(src) + (size_t)off * 512;
        uint4* d16 = reinterpret_cast<uint4*>(dst) + (size_t)off * 256;
        float4 a = s4[2 * tid];
        float4 b = s4[2 * tid + 1];
        uint4 o;
        o.x = h2(a.x, a.y); o.y = h2(a.z, a.w);
        o.z = h2(b.x, b.y); o.w = h2(b.z, b.w);
        d16[tid] = o;
    } else {
        int word = (bid - 4096) * 256 + tid;
        const int4* m4 = reinterpret_cast<const int4*>(mask) + (size_t)word * 8;
        unsigned bits = 0;
#pragma unroll
        for (int i = 0; i < 8; i++) {
            int4 mv = m4[i];
            bits |= (mv.x != 0 ? 1u : 0u) << (i * 4 + 0);
            bits |= (mv.y != 0 ? 1u : 0u) << (i * 4 + 1);
            bits |= (mv.z != 0 ? 1u : 0u) << (i * 4 + 2);
            bits |= (mv.w != 0 ? 1u : 0u) << (i * 4 + 3);
        }
        g_mpack[word] = bits;
    }
}

// ---------------------------------------------------------------------------
// Kernel 2: fused flash attention (R9 proven body) + 64 bonus W-convert blocks
// grid (9,16,4): x<8 -> attention tile; x==8 -> convert 16 rows of W.
// ---------------------------------------------------------------------------
#define ATTN_STG 18432
#define ATTN_SMEM (3 * ATTN_STG)

__global__ __launch_bounds__(256, 2) void attn_kernel(
    const float* __restrict__ q, const float* __restrict__ W) {
    extern __shared__ __align__(16) char dynsm[];
    const uint32_t smb = smem_u32(dynsm);

    const int tid = threadIdx.x;

    if (blockIdx.x == 8) {
        // ---- bonus block: convert 16 rows of W (16384 floats) to fp16 ----
        const int off = blockIdx.z * 16 + blockIdx.y;  // 0..63
        const float4* s4 = reinterpret_cast<const float4*>(W) + (size_t)off * 4096;
        uint4* d16 = reinterpret_cast<uint4*>(g_wh) + (size_t)off * 2048;
#pragma unroll
        for (int t = 0; t < 8; t++) {
            int i = tid + t * 256;  // 0..2047
            float4 a = s4[2 * i];
            float4 b = s4[2 * i + 1];
            uint4 o;
            o.x = h2(a.x, a.y); o.y = h2(a.z, a.w);
            o.z = h2(b.x, b.y); o.w = h2(b.z, b.w);
            d16[i] = o;
        }
        return;
    }

    const int w = tid >> 5;
    const int lane = tid & 31;
    const int g = lane >> 2;
    const int j = lane & 3;
    const int lr = lane & 7;
    const int grp = lane >> 3;

    const int qt = blockIdx.x;
    const int h = blockIdx.y;
    const int b = blockIdx.z;
    const int q0 = qt * 128;

    const float* qb = q + ((size_t)b * SEQ + q0) * EMB + h * HD;
    const __half* kbp = g_kh + (size_t)b * SEQ * EMB + h * HD;
    const __half* vbp = g_vh + (size_t)b * SEQ * EMB + h * HD;

    const float C = 0.125f * 1.44269504f;

    // ---- stage Q (128x64) fp32 -> fp16 into stage0 directly ----
#pragma unroll
    for (int t = 0; t < 8; t++) {
        int idx = tid + t * 256;
        int row = idx >> 4, c4 = idx & 15;
        float4 val = *reinterpret_cast<const float4*>(qb + (size_t)row * EMB + c4 * 4);
        *reinterpret_cast<uint2*>(dynsm + row * 144 + c4 * 8) =
            make_uint2(h2(val.x, val.y), h2(val.z, val.w));
    }
    __syncthreads();

    unsigned qa[4][4];
#pragma unroll
    for (int kk = 0; kk < 4; kk++) {
        uint32_t addr = smb + (w * 16 + lr + 8 * (grp & 1)) * 144 +
                        kk * 32 + (grp >> 1) * 16;
        ldsm4(qa[kk], addr);
    }
    __syncthreads();

    auto issueKV = [&](int kn, uint32_t st) {
#pragma unroll
        for (int t = 0; t < 2; t++) {
            int c = tid + t * 256;
            int row = c >> 3, col = c & 7;
            cpa16(st + row * 144 + col * 16,
                  kbp + (size_t)(kn * 64 + row) * EMB + col * 8);
            cpa16(st + (64 + row) * 144 + col * 16,
                  vbp + (size_t)(kn * 64 + row) * EMB + col * 8);
        }
        cp_commit();
    };

    issueKV(0, smb);
    issueKV(1, smb + ATTN_STG);

    float oacc[8][4];
#pragma unroll
    for (int n = 0; n < 8; n++)
#pragma unroll
        for (int i = 0; i < 4; i++) oacc[n][i] = 0.f;

    float lp0 = 0.f, lp1 = 0.f;

    const unsigned* mp0 = g_mpack + ((size_t)b * SEQ + q0 + w * 16 + g) * 32;
    const unsigned* mp1 = mp0 + 8 * 32;

    int c3 = 0, i3 = 2;
    for (int kb = 0; kb < 16; kb++) {
        const uint32_t st = smb + c3 * ATTN_STG;
        if (kb < 15) cp_wait1(); else cp_wait0();
        __syncthreads();

        float sacc[8][4];
#pragma unroll
        for (int n = 0; n < 8; n++) {
            sacc[n][0] = sacc[n][1] = sacc[n][2] = sacc[n][3] = 0.f;
            unsigned bk[8];
            uint32_t rb = st + (n * 8 + lr) * 144 + grp * 16;
            ldsm4(bk, rb);
            ldsm4(bk + 4, rb + 64);
#pragma unroll
            for (int kk = 0; kk < 4; kk++) mma_f16(sacc[n], qa[kk], &bk[2 * kk]);
        }

        uint2 w0 = *reinterpret_cast<const uint2*>(mp0 + 2 * kb);
        uint2 w1 = *reinterpret_cast<const uint2*>(mp1 + 2 * kb);
        unsigned long long mm0 = (unsigned long long)w0.x | ((unsigned long long)w0.y << 32);
        unsigned long long mm1 = (unsigned long long)w1.x | ((unsigned long long)w1.y << 32);

#pragma unroll
        for (int n = 0; n < 8; n++) {
            int p = n * 8 + 2 * j;
            float e0 = ((mm0 >> p) & 1) ? ex2(sacc[n][0] * C) : 0.f;
            float e1 = ((mm0 >> (p + 1)) & 1) ? ex2(sacc[n][1] * C) : 0.f;
            float e2 = ((mm1 >> p) & 1) ? ex2(sacc[n][2] * C) : 0.f;
            float e3 = ((mm1 >> (p + 1)) & 1) ? ex2(sacc[n][3] * C) : 0.f;
            sacc[n][0] = e0; sacc[n][1] = e1; sacc[n][2] = e2; sacc[n][3] = e3;
            lp0 += e0 + e1;
            lp1 += e2 + e3;
        }

#pragma unroll
        for (int t = 0; t < 4; t++) {
            unsigned pa[4];
            pa[0] = h2(sacc[2 * t][0], sacc[2 * t][1]);
            pa[1] = h2(sacc[2 * t][2], sacc[2 * t][3]);
            pa[2] = h2(sacc[2 * t + 1][0], sacc[2 * t + 1][1]);
            pa[3] = h2(sacc[2 * t + 1][2], sacc[2 * t + 1][3]);
#pragma unroll
            for (int ndp = 0; ndp < 4; ndp++) {
                unsigned bv[4];
                uint32_t addr = st + (64 + 16 * t + lr + 8 * (grp & 1)) * 144 +
                                ndp * 32 + (grp >> 1) * 16;
                ldsm4t(bv, addr);
                mma_f16(oacc[2 * ndp], pa, bv);
                mma_f16(oacc[2 * ndp + 1], pa, bv + 2);
            }
        }

        if (kb + 2 < 16) issueKV(kb + 2, smb + i3 * ATTN_STG);

        c3 = (c3 == 2) ? 0 : c3 + 1;
        i3 = (i3 == 2) ? 0 : i3 + 1;
    }

    lp0 += __shfl_xor_sync(0xffffffffu, lp0, 1);
    lp0 += __shfl_xor_sync(0xffffffffu, lp0, 2);
    lp1 += __shfl_xor_sync(0xffffffffu, lp1, 1);
    lp1 += __shfl_xor_sync(0xffffffffu, lp1, 2);

    float inv0 = 1.f / lp0, inv1 = 1.f / lp1;
    __half* obase = g_xh + ((size_t)b * SEQ + q0 + w * 16 + g) * EMB + h * HD;
#pragma unroll
    for (int nd = 0; nd < 8; nd++) {
        int col = nd * 8 + 2 * j;
        *reinterpret_cast<unsigned*>(obase + col) =
            h2(oacc[nd][0] * inv0, oacc[nd][1] * inv0);
        *reinterpret_cast<unsigned*>(obase + (size_t)8 * EMB + col) =
            h2(oacc[nd][2] * inv1, oacc[nd][3] * inv1);
    }
}

// ---------------------------------------------------------------------------
// Kernel 3: out = X (4096x1024) @ W^T + b, fp16 mma + ldmatrix,
// K-chunk 64 per stage (2 reg sub-chunks), 3-stage cp.async, 1 barrier/iter.
// ---------------------------------------------------------------------------
#define PROJ_AST 18432
#define PROJ_SMEM (6 * PROJ_AST)

__global__ __launch_bounds__(256, 2) void proj_kernel(
    const float* __restrict__ bias, float* __restrict__ out) {
    extern __shared__ __align__(16) char dynsm[];
    const uint32_t smb = smem_u32(dynsm);

    const int tid = threadIdx.x;
    const int w = tid >> 5, lane = tid & 31, g = lane >> 2, j = lane & 3;
    const int lr = lane & 7, grp = lane >> 3;
    const int wm = (w >> 2) * 64;
    const int wn = (w & 3) * 32;
    const int bm = blockIdx.y * 128;
    const int bn = blockIdx.x * 128;

    const __half* xb = g_xh + (size_t)bm * EMB;
    const __half* wb = g_wh + (size_t)bn * EMB;

    auto issue = [&](int kb, int stg) {
        uint32_t au = smb + stg * PROJ_AST;
        uint32_t bu = smb + 3 * PROJ_AST + stg * PROJ_AST;
#pragma unroll
        for (int t = 0; t < 4; t++) {
            int c = tid + t * 256;
            int row = c >> 3, col = c & 7;
            cpa16(au + row * 144 + col * 16,
                  xb + (size_t)row * EMB + kb * 64 + col * 8);
            cpa16(bu + row * 144 + col * 16,
                  wb + (size_t)row * EMB + kb * 64 + col * 8);
        }
        cp_commit();
    };

    issue(0, 0);
    issue(1, 1);

    float acc[4][4][4];
#pragma unroll
    for (int mi = 0; mi < 4; mi++)
#pragma unroll
        for (int ni = 0; ni < 4; ni++)
#pragma unroll
            for (int i = 0; i < 4; i++) acc[mi][ni][i] = 0.f;

    int c3 = 0, i3 = 2;
    for (int kb = 0; kb < 16; kb++) {
        const uint32_t au = smb + c3 * PROJ_AST;
        const uint32_t bu = smb + 3 * PROJ_AST + c3 * PROJ_AST;
        if (kb < 15) cp_wait1(); else cp_wait0();
        __syncthreads();

#pragma unroll
        for (int half = 0; half < 2; half++) {
            const int cb = half * 64;
            unsigned af[4][2][4];
#pragma unroll
            for (int mi = 0; mi < 4; mi++)
#pragma unroll
                for (int kk = 0; kk < 2; kk++) {
                    uint32_t addr = au + (wm + mi * 16 + lr + 8 * (grp & 1)) * 144 +
                                    cb + kk * 32 + (grp >> 1) * 16;
                    ldsm4(af[mi][kk], addr);
                }
#pragma unroll
            for (int ni = 0; ni < 4; ni++) {
                unsigned bf[4];
                uint32_t addr = bu + (wn + ni * 8 + lr) * 144 + cb + grp * 16;
                ldsm4(bf, addr);
#pragma unroll
                for (int mi = 0; mi < 4; mi++) {
                    mma_f16(acc[mi][ni], af[mi][0], bf);
                    mma_f16(acc[mi][ni], af[mi][1], bf + 2);
                }
            }
        }

        if (kb + 2 < 16) issue(kb + 2, i3);

        c3 = (c3 == 2) ? 0 : c3 + 1;
        i3 = (i3 == 2) ? 0 : i3 + 1;
    }

#pragma unroll
    for (int mi = 0; mi < 4; mi++) {
        int r = bm + wm + mi * 16 + g;
#pragma unroll
        for (int ni = 0; ni < 4; ni++) {
            int col = bn + wn + ni * 8 + 2 * j;
            float2 bb = *reinterpret_cast<const float2*>(bias + col);
            *reinterpret_cast<float2*>(out + (size_t)r * EMB + col) =
                make_float2(acc[mi][ni][0] + bb.x, acc[mi][ni][1] + bb.y);
            *reinterpret_cast<float2*>(out + (size_t)(r + 8) * EMB + col) =
                make_float2(acc[mi][ni][2] + bb.x, acc[mi][ni][3] + bb.y);
        }
    }
}

// ---------------------------------------------------------------------------
extern "C" void kernel_launch(void* const* d_in, const int* in_sizes, int n_in,
                              void* d_out, int out_size) {
    const float* q = (const float*)d_in[0];
    const float* k = (const float*)d_in[1];
    const float* v = (const float*)d_in[2];
    const int* mask = (const int*)d_in[3];
    const float* Wm = (const float*)d_in[4];
    const float* bias = (const float*)d_in[5];
    float* out = (float*)d_out;

    static bool attr_done = false;
    if (!attr_done) {
        cudaFuncSetAttribute(attn_kernel, cudaFuncAttributeMaxDynamicSharedMemorySize,
                             ATTN_SMEM);
        cudaFuncSetAttribute(proj_kernel, cudaFuncAttributeMaxDynamicSharedMemorySize,
                             PROJ_SMEM);
        attr_done = true;
    }

    pre_kernel<<<4608, 256>>>(k, v, mask);

    dim3 ga(9, NH, NB);  // x==8 lane converts W
    attn_kernel<<<ga, 256, ATTN_SMEM>>>(q, Wm);

    dim3 gp(8, 32);
    proj_kernel<<<gp, 256, PROJ_SMEM>>>(bias, out);
}

// round 15
// speedup vs baseline: 1.0711x; 1.0178x over previous
#include <cuda_runtime.h>
#include <cuda_fp16.h>
#include <cstdint>

#define SEQ 1024
#define NB 4
#define NH 16
#define HD 64
#define EMB 1024

// scratch: fp16 copies of k/v/W, fp16 attention output, packed mask
__device__ __align__(16) __half g_kh[NB * SEQ * EMB];
__device__ __align__(16) __half g_vh[NB * SEQ * EMB];
__device__ __align__(16) __half g_wh[EMB * EMB];
__device__ __align__(16) __half g_xh[NB * SEQ * EMB];
__device__ __align__(16) unsigned g_mpack[NB * SEQ * (SEQ / 32)];

__device__ __forceinline__ unsigned h2(float lo, float hi) {
    __half2 h = __floats2half2_rn(lo, hi);
    return *reinterpret_cast<unsigned*>(&h);
}

__device__ __forceinline__ float ex2(float x) {
    float r;
    asm("ex2.approx.ftz.f32 %0, %1;" : "=f"(r) : "f"(x));
    return r;
}

__device__ __forceinline__ void mma_f16(float* d, const unsigned* a, const unsigned* b) {
    asm volatile(
        "mma.sync.aligned.m16n8k16.row.col.f32.f16.f16.f32 "
        "{%0,%1,%2,%3}, {%4,%5,%6,%7}, {%8,%9}, {%0,%1,%2,%3};\n"
        : "+f"(d[0]), "+f"(d[1]), "+f"(d[2]), "+f"(d[3])
        : "r"(a[0]), "r"(a[1]), "r"(a[2]), "r"(a[3]), "r"(b[0]), "r"(b[1]));
}

__device__ __forceinline__ uint32_t smem_u32(const void* p) {
    uint32_t a;
    asm("{ .reg .u64 t; cvta.to.shared.u64 t, %1; cvt.u32.u64 %0, t; }" : "=r"(a) : "l"(p));
    return a;
}

__device__ __forceinline__ void ldsm4(unsigned* r, uint32_t a) {
    asm volatile("ldmatrix.sync.aligned.m8n8.x4.shared.b16 {%0,%1,%2,%3}, [%4];"
                 : "=r"(r[0]), "=r"(r[1]), "=r"(r[2]), "=r"(r[3]) : "r"(a));
}

__device__ __forceinline__ void ldsm4t(unsigned* r, uint32_t a) {
    asm volatile("ldmatrix.sync.aligned.m8n8.x4.trans.shared.b16 {%0,%1,%2,%3}, [%4];"
                 : "=r"(r[0]), "=r"(r[1]), "=r"(r[2]), "=r"(r[3]) : "r"(a));
}

__device__ __forceinline__ void cpa16(uint32_t dst, const void* src) {
    asm volatile("cp.async.cg.shared.global [%0], [%1], 16;" ::"r"(dst), "l"(src) : "memory");
}
__device__ __forceinline__ void cp_commit() {
    asm volatile("cp.async.commit_group;" ::: "memory");
}
__device__ __forceinline__ void cp_wait0() {
    asm volatile("cp.async.wait_group 0;" ::: "memory");
}
__device__ __forceinline__ void cp_wait1() {
    asm volatile("cp.async.wait_group 1;" ::: "memory");
}

// ---------------------------------------------------------------------------
// Kernel 1: preamble — fp32->fp16 of k/v + mask bitpack, ROLE-INTERLEAVED so
// heavy mask blocks spread uniformly across dispatch waves (no pure-mask tail).
// 4608 blocks: bid%9==8 -> mask block (bid/9, 512 total);
//              else     -> conversion block (bid/9*8 + bid%9, 4096 total).
// Conversion block = 2048 floats: thread does 2 LDG.128 -> 1 STG.128.
// ---------------------------------------------------------------------------
__global__ __launch_bounds__(256) void pre_kernel(
    const float* __restrict__ k, const float* __restrict__ v,
    const int* __restrict__ mask) {
    const int bid = blockIdx.x, tid = threadIdx.x;
    const int mi = bid / 9;
    const int rem = bid - mi * 9;
    if (rem != 8) {
        const int cb = mi * 8 + rem;  // 0..4095
        const float* src;
        __half* dst;
        int off;
        if (cb < 2048) { src = k; dst = g_kh; off = cb; }
        else           { src = v; dst = g_vh; off = cb - 2048; }
        const float4* s4 = reinterpret_cast<const float4*>(src) + (size_t)off * 512;
        uint4* d16 = reinterpret_cast<uint4*>(dst) + (size_t)off * 256;
        float4 a = s4[2 * tid];
        float4 b = s4[2 * tid + 1];
        uint4 o;
        o.x = h2(a.x, a.y); o.y = h2(a.z, a.w);
        o.z = h2(b.x, b.y); o.w = h2(b.z, b.w);
        d16[tid] = o;
    } else {
        int word = mi * 256 + tid;  // 512 blocks x 256 = 131072 words
        const int4* m4 = reinterpret_cast<const int4*>(mask) + (size_t)word * 8;
        unsigned bits = 0;
#pragma unroll
        for (int i = 0; i < 8; i++) {
            int4 mv = m4[i];
            bits |= (mv.x != 0 ? 1u : 0u) << (i * 4 + 0);
            bits |= (mv.y != 0 ? 1u : 0u) << (i * 4 + 1);
            bits |= (mv.z != 0 ? 1u : 0u) << (i * 4 + 2);
            bits |= (mv.w != 0 ? 1u : 0u) << (i * 4 + 3);
        }
        g_mpack[word] = bits;
    }
}

// ---------------------------------------------------------------------------
// Kernel 2: fused flash attention (proven body) + 64 bonus W-convert blocks
// grid (9,16,4): x<8 -> attention tile; x==8 -> convert 16 rows of W.
// ---------------------------------------------------------------------------
#define ATTN_STG 18432
#define ATTN_SMEM (3 * ATTN_STG)

__global__ __launch_bounds__(256, 2) void attn_kernel(
    const float* __restrict__ q, const float* __restrict__ W) {
    extern __shared__ __align__(16) char dynsm[];
    const uint32_t smb = smem_u32(dynsm);

    const int tid = threadIdx.x;

    if (blockIdx.x == 8) {
        // ---- bonus block: convert 16 rows of W (16384 floats) to fp16 ----
        const int off = blockIdx.z * 16 + blockIdx.y;  // 0..63
        const float4* s4 = reinterpret_cast<const float4*>(W) + (size_t)off * 4096;
        uint4* d16 = reinterpret_cast<uint4*>(g_wh) + (size_t)off * 2048;
#pragma unroll
        for (int t = 0; t < 8; t++) {
            int i = tid + t * 256;  // 0..2047
            float4 a = s4[2 * i];
            float4 b = s4[2 * i + 1];
            uint4 o;
            o.x = h2(a.x, a.y); o.y = h2(a.z, a.w);
            o.z = h2(b.x, b.y); o.w = h2(b.z, b.w);
            d16[i] = o;
        }
        return;
    }

    const int w = tid >> 5;
    const int lane = tid & 31;
    const int g = lane >> 2;
    const int j = lane & 3;
    const int lr = lane & 7;
    const int grp = lane >> 3;

    const int qt = blockIdx.x;
    const int h = blockIdx.y;
    const int b = blockIdx.z;
    const int q0 = qt * 128;

    const float* qb = q + ((size_t)b * SEQ + q0) * EMB + h * HD;
    const __half* kbp = g_kh + (size_t)b * SEQ * EMB + h * HD;
    const __half* vbp = g_vh + (size_t)b * SEQ * EMB + h * HD;

    const float C = 0.125f * 1.44269504f;

    // ---- stage Q (128x64) fp32 -> fp16 into stage0 directly ----
#pragma unroll
    for (int t = 0; t < 8; t++) {
        int idx = tid + t * 256;
        int row = idx >> 4, c4 = idx & 15;
        float4 val = *reinterpret_cast<const float4*>(qb + (size_t)row * EMB + c4 * 4);
        *reinterpret_cast<uint2*>(dynsm + row * 144 + c4 * 8) =
            make_uint2(h2(val.x, val.y), h2(val.z, val.w));
    }
    __syncthreads();

    unsigned qa[4][4];
#pragma unroll
    for (int kk = 0; kk < 4; kk++) {
        uint32_t addr = smb + (w * 16 + lr + 8 * (grp & 1)) * 144 +
                        kk * 32 + (grp >> 1) * 16;
        ldsm4(qa[kk], addr);
    }
    __syncthreads();

    auto issueKV = [&](int kn, uint32_t st) {
#pragma unroll
        for (int t = 0; t < 2; t++) {
            int c = tid + t * 256;
            int row = c >> 3, col = c & 7;
            cpa16(st + row * 144 + col * 16,
                  kbp + (size_t)(kn * 64 + row) * EMB + col * 8);
            cpa16(st + (64 + row) * 144 + col * 16,
                  vbp + (size_t)(kn * 64 + row) * EMB + col * 8);
        }
        cp_commit();
    };

    issueKV(0, smb);
    issueKV(1, smb + ATTN_STG);

    float oacc[8][4];
#pragma unroll
    for (int n = 0; n < 8; n++)
#pragma unroll
        for (int i = 0; i < 4; i++) oacc[n][i] = 0.f;

    float lp0 = 0.f, lp1 = 0.f;

    const unsigned* mp0 = g_mpack + ((size_t)b * SEQ + q0 + w * 16 + g) * 32;
    const unsigned* mp1 = mp0 + 8 * 32;

    int c3 = 0, i3 = 2;
    for (int kb = 0; kb < 16; kb++) {
        const uint32_t st = smb + c3 * ATTN_STG;
        if (kb < 15) cp_wait1(); else cp_wait0();
        __syncthreads();

        float sacc[8][4];
#pragma unroll
        for (int n = 0; n < 8; n++) {
            sacc[n][0] = sacc[n][1] = sacc[n][2] = sacc[n][3] = 0.f;
            unsigned bk[8];
            uint32_t rb = st + (n * 8 + lr) * 144 + grp * 16;
            ldsm4(bk, rb);
            ldsm4(bk + 4, rb + 64);
#pragma unroll
            for (int kk = 0; kk < 4; kk++) mma_f16(sacc[n], qa[kk], &bk[2 * kk]);
        }

        uint2 w0 = *reinterpret_cast<const uint2*>(mp0 + 2 * kb);
        uint2 w1 = *reinterpret_cast<const uint2*>(mp1 + 2 * kb);
        unsigned long long mm0 = (unsigned long long)w0.x | ((unsigned long long)w0.y << 32);
        unsigned long long mm1 = (unsigned long long)w1.x | ((unsigned long long)w1.y << 32);

#pragma unroll
        for (int n = 0; n < 8; n++) {
            int p = n * 8 + 2 * j;
            float e0 = ((mm0 >> p) & 1) ? ex2(sacc[n][0] * C) : 0.f;
            float e1 = ((mm0 >> (p + 1)) & 1) ? ex2(sacc[n][1] * C) : 0.f;
            float e2 = ((mm1 >> p) & 1) ? ex2(sacc[n][2] * C) : 0.f;
            float e3 = ((mm1 >> (p + 1)) & 1) ? ex2(sacc[n][3] * C) : 0.f;
            sacc[n][0] = e0; sacc[n][1] = e1; sacc[n][2] = e2; sacc[n][3] = e3;
            lp0 += e0 + e1;
            lp1 += e2 + e3;
        }

#pragma unroll
        for (int t = 0; t < 4; t++) {
            unsigned pa[4];
            pa[0] = h2(sacc[2 * t][0], sacc[2 * t][1]);
            pa[1] = h2(sacc[2 * t][2], sacc[2 * t][3]);
            pa[2] = h2(sacc[2 * t + 1][0], sacc[2 * t + 1][1]);
            pa[3] = h2(sacc[2 * t + 1][2], sacc[2 * t + 1][3]);
#pragma unroll
            for (int ndp = 0; ndp < 4; ndp++) {
                unsigned bv[4];
                uint32_t addr = st + (64 + 16 * t + lr + 8 * (grp & 1)) * 144 +
                                ndp * 32 + (grp >> 1) * 16;
                ldsm4t(bv, addr);
                mma_f16(oacc[2 * ndp], pa, bv);
                mma_f16(oacc[2 * ndp + 1], pa, bv + 2);
            }
        }

        if (kb + 2 < 16) issueKV(kb + 2, smb + i3 * ATTN_STG);

        c3 = (c3 == 2) ? 0 : c3 + 1;
        i3 = (i3 == 2) ? 0 : i3 + 1;
    }

    lp0 += __shfl_xor_sync(0xffffffffu, lp0, 1);
    lp0 += __shfl_xor_sync(0xffffffffu, lp0, 2);
    lp1 += __shfl_xor_sync(0xffffffffu, lp1, 1);
    lp1 += __shfl_xor_sync(0xffffffffu, lp1, 2);

    float inv0 = 1.f / lp0, inv1 = 1.f / lp1;
    __half* obase = g_xh + ((size_t)b * SEQ + q0 + w * 16 + g) * EMB + h * HD;
#pragma unroll
    for (int nd = 0; nd < 8; nd++) {
        int col = nd * 8 + 2 * j;
        *reinterpret_cast<unsigned*>(obase + col) =
            h2(oacc[nd][0] * inv0, oacc[nd][1] * inv0);
        *reinterpret_cast<unsigned*>(obase + (size_t)8 * EMB + col) =
            h2(oacc[nd][2] * inv1, oacc[nd][3] * inv1);
    }
}

// ---------------------------------------------------------------------------
// Kernel 3: out = X (4096x1024) @ W^T + b, fp16 mma + ldmatrix,
// K-chunk 64 per stage (2 reg sub-chunks), 3-stage cp.async, 1 barrier/iter.
// ---------------------------------------------------------------------------
#define PROJ_AST 18432
#define PROJ_SMEM (6 * PROJ_AST)

__global__ __launch_bounds__(256, 2) void proj_kernel(
    const float* __restrict__ bias, float* __restrict__ out) {
    extern __shared__ __align__(16) char dynsm[];
    const uint32_t smb = smem_u32(dynsm);

    const int tid = threadIdx.x;
    const int w = tid >> 5, lane = tid & 31, g = lane >> 2, j = lane & 3;
    const int lr = lane & 7, grp = lane >> 3;
    const int wm = (w >> 2) * 64;
    const int wn = (w & 3) * 32;
    const int bm = blockIdx.y * 128;
    const int bn = blockIdx.x * 128;

    const __half* xb = g_xh + (size_t)bm * EMB;
    const __half* wb = g_wh + (size_t)bn * EMB;

    auto issue = [&](int kb, int stg) {
        uint32_t au = smb + stg * PROJ_AST;
        uint32_t bu = smb + 3 * PROJ_AST + stg * PROJ_AST;
#pragma unroll
        for (int t = 0; t < 4; t++) {
            int c = tid + t * 256;
            int row = c >> 3, col = c & 7;
            cpa16(au + row * 144 + col * 16,
                  xb + (size_t)row * EMB + kb * 64 + col * 8);
            cpa16(bu + row * 144 + col * 16,
                  wb + (size_t)row * EMB + kb * 64 + col * 8);
        }
        cp_commit();
    };

    issue(0, 0);
    issue(1, 1);

    float acc[4][4][4];
#pragma unroll
    for (int mi = 0; mi < 4; mi++)
#pragma unroll
        for (int ni = 0; ni < 4; ni++)
#pragma unroll
            for (int i = 0; i < 4; i++) acc[mi][ni][i] = 0.f;

    int c3 = 0, i3 = 2;
    for (int kb = 0; kb < 16; kb++) {
        const uint32_t au = smb + c3 * PROJ_AST;
        const uint32_t bu = smb + 3 * PROJ_AST + c3 * PROJ_AST;
        if (kb < 15) cp_wait1(); else cp_wait0();
        __syncthreads();

#pragma unroll
        for (int half = 0; half < 2; half++) {
            const int cb = half * 64;
            unsigned af[4][2][4];
#pragma unroll
            for (int mi = 0; mi < 4; mi++)
#pragma unroll
                for (int kk = 0; kk < 2; kk++) {
                    uint32_t addr = au + (wm + mi * 16 + lr + 8 * (grp & 1)) * 144 +
                                    cb + kk * 32 + (grp >> 1) * 16;
                    ldsm4(af[mi][kk], addr);
                }
#pragma unroll
            for (int ni = 0; ni < 4; ni++) {
                unsigned bf[4];
                uint32_t addr = bu + (wn + ni * 8 + lr) * 144 + cb + grp * 16;
                ldsm4(bf, addr);
#pragma unroll
                for (int mi = 0; mi < 4; mi++) {
                    mma_f16(acc[mi][ni], af[mi][0], bf);
                    mma_f16(acc[mi][ni], af[mi][1], bf + 2);
                }
            }
        }

        if (kb + 2 < 16) issue(kb + 2, i3);

        c3 = (c3 == 2) ? 0 : c3 + 1;
        i3 = (i3 == 2) ? 0 : i3 + 1;
    }

#pragma unroll
    for (int mi = 0; mi < 4; mi++) {
        int r = bm + wm + mi * 16 + g;
#pragma unroll
        for (int ni = 0; ni < 4; ni++) {
            int col = bn + wn + ni * 8 + 2 * j;
            float2 bb = *reinterpret_cast<const float2*>(bias + col);
            *reinterpret_cast<float2*>(out + (size_t)r * EMB + col) =
                make_float2(acc[mi][ni][0] + bb.x, acc[mi][ni][1] + bb.y);
            *reinterpret_cast<float2*>(out + (size_t)(r + 8) * EMB + col) =
                make_float2(acc[mi][ni][2] + bb.x, acc[mi][ni][3] + bb.y);
        }
    }
}

// ---------------------------------------------------------------------------
extern "C" void kernel_launch(void* const* d_in, const int* in_sizes, int n_in,
                              void* d_out, int out_size) {
    const float* q = (const float*)d_in[0];
    const float* k = (const float*)d_in[1];
    const float* v = (const float*)d_in[2];
    const int* mask = (const int*)d_in[3];
    const float* Wm = (const float*)d_in[4];
    const float* bias = (const float*)d_in[5];
    float* out = (float*)d_out;

    static bool attr_done = false;
    if (!attr_done) {
        cudaFuncSetAttribute(attn_kernel, cudaFuncAttributeMaxDynamicSharedMemorySize,
                             ATTN_SMEM);
        cudaFuncSetAttribute(proj_kernel, cudaFuncAttributeMaxDynamicSharedMemorySize,
                             PROJ_SMEM);
        attr_done = true;
    }

    pre_kernel<<<4608, 256>>>(k, v, mask);

    dim3 ga(9, NH, NB);  // x==8 lane converts W
    attn_kernel<<<ga, 256, ATTN_SMEM>>>(q, Wm);

    dim3 gp(8, 32);
    proj_kernel<<<gp, 256, PROJ_SMEM>>>(bias, out);
}

// round 16
// speedup vs baseline: 1.0723x; 1.0011x over previous
#include <cuda_runtime.h>
#include <cuda_fp16.h>
#include <cstdint>

#define SEQ 1024
#define NB 4
#define NH 16
#define HD 64
#define EMB 1024

// scratch: fp16 copies of k/v/W, fp16 attention output, packed mask
__device__ __align__(16) __half g_kh[NB * SEQ * EMB];
__device__ __align__(16) __half g_vh[NB * SEQ * EMB];
__device__ __align__(16) __half g_wh[EMB * EMB];
__device__ __align__(16) __half g_xh[NB * SEQ * EMB];
__device__ __align__(16) unsigned g_mpack[NB * SEQ * (SEQ / 32)];

__device__ __forceinline__ unsigned h2(float lo, float hi) {
    __half2 h = __floats2half2_rn(lo, hi);
    return *reinterpret_cast<unsigned*>(&h);
}

__device__ __forceinline__ float ex2(float x) {
    float r;
    asm("ex2.approx.ftz.f32 %0, %1;" : "=f"(r) : "f"(x));
    return r;
}

__device__ __forceinline__ void mma_f16(float* d, const unsigned* a, const unsigned* b) {
    asm volatile(
        "mma.sync.aligned.m16n8k16.row.col.f32.f16.f16.f32 "
        "{%0,%1,%2,%3}, {%4,%5,%6,%7}, {%8,%9}, {%0,%1,%2,%3};\n"
        : "+f"(d[0]), "+f"(d[1]), "+f"(d[2]), "+f"(d[3])
        : "r"(a[0]), "r"(a[1]), "r"(a[2]), "r"(a[3]), "r"(b[0]), "r"(b[1]));
}

__device__ __forceinline__ uint32_t smem_u32(const void* p) {
    uint32_t a;
    asm("{ .reg .u64 t; cvta.to.shared.u64 t, %1; cvt.u32.u64 %0, t; }" : "=r"(a) : "l"(p));
    return a;
}

__device__ __forceinline__ void ldsm4(unsigned* r, uint32_t a) {
    asm volatile("ldmatrix.sync.aligned.m8n8.x4.shared.b16 {%0,%1,%2,%3}, [%4];"
                 : "=r"(r[0]), "=r"(r[1]), "=r"(r[2]), "=r"(r[3]) : "r"(a));
}

__device__ __forceinline__ void ldsm4t(unsigned* r, uint32_t a) {
    asm volatile("ldmatrix.sync.aligned.m8n8.x4.trans.shared.b16 {%0,%1,%2,%3}, [%4];"
                 : "=r"(r[0]), "=r"(r[1]), "=r"(r[2]), "=r"(r[3]) : "r"(a));
}

__device__ __forceinline__ void cpa16(uint32_t dst, const void* src) {
    asm volatile("cp.async.cg.shared.global [%0], [%1], 16;" ::"r"(dst), "l"(src) : "memory");
}
__device__ __forceinline__ void cp_commit() {
    asm volatile("cp.async.commit_group;" ::: "memory");
}
__device__ __forceinline__ void cp_wait0() {
    asm volatile("cp.async.wait_group 0;" ::: "memory");
}
__device__ __forceinline__ void cp_wait1() {
    asm volatile("cp.async.wait_group 1;" ::: "memory");
}

// ---------------------------------------------------------------------------
// Kernel 1: preamble — fp32->fp16 of k/v + mask bitpack, role-interleaved AND
// per-block-duration-balanced: conversion block moves 12 KB, mask block 16 KB.
// 5120 blocks: bid%5==4 -> mask block (bid/5, 1024 total; 128 words each,
//                          threads 0-127 pack one word apiece);
//              else     -> conversion block (bid/5*4 + bid%5, 4096 total).
// ---------------------------------------------------------------------------
__global__ __launch_bounds__(256) void pre_kernel(
    const float* __restrict__ k, const float* __restrict__ v,
    const int* __restrict__ mask) {
    const int bid = blockIdx.x, tid = threadIdx.x;
    const int mi = bid / 5;
    const int rem = bid - mi * 5;
    if (rem != 4) {
        const int cb = mi * 4 + rem;  // 0..4095
        const float* src;
        __half* dst;
        int off;
        if (cb < 2048) { src = k; dst = g_kh; off = cb; }
        else           { src = v; dst = g_vh; off = cb - 2048; }
        const float4* s4 = reinterpret_cast<const float4*>(src) + (size_t)off * 512;
        uint4* d16 = reinterpret_cast<uint4*>(dst) + (size_t)off * 256;
        float4 a = s4[2 * tid];
        float4 b = s4[2 * tid + 1];
        uint4 o;
        o.x = h2(a.x, a.y); o.y = h2(a.z, a.w);
        o.z = h2(b.x, b.y); o.w = h2(b.z, b.w);
        d16[tid] = o;
    } else if (tid < 128) {
        int word = mi * 128 + tid;  // 1024 blocks x 128 = 131072 words
        const int4* m4 = reinterpret_cast<const int4*>(mask) + (size_t)word * 8;
        unsigned bits = 0;
#pragma unroll
        for (int i = 0; i < 8; i++) {
            int4 mv = m4[i];
            bits |= (mv.x != 0 ? 1u : 0u) << (i * 4 + 0);
            bits |= (mv.y != 0 ? 1u : 0u) << (i * 4 + 1);
            bits |= (mv.z != 0 ? 1u : 0u) << (i * 4 + 2);
            bits |= (mv.w != 0 ? 1u : 0u) << (i * 4 + 3);
        }
        g_mpack[word] = bits;
    }
}

// ---------------------------------------------------------------------------
// Kernel 2: fused flash attention (proven body) + 64 bonus W-convert blocks
// grid (9,16,4): x<8 -> attention tile; x==8 -> convert 16 rows of W.
// ---------------------------------------------------------------------------
#define ATTN_STG 18432
#define ATTN_SMEM (3 * ATTN_STG)

__global__ __launch_bounds__(256, 2) void attn_kernel(
    const float* __restrict__ q, const float* __restrict__ W) {
    extern __shared__ __align__(16) char dynsm[];
    const uint32_t smb = smem_u32(dynsm);

    const int tid = threadIdx.x;

    if (blockIdx.x == 8) {
        // ---- bonus block: convert 16 rows of W (16384 floats) to fp16 ----
        const int off = blockIdx.z * 16 + blockIdx.y;  // 0..63
        const float4* s4 = reinterpret_cast<const float4*>(W) + (size_t)off * 4096;
        uint4* d16 = reinterpret_cast<uint4*>(g_wh) + (size_t)off * 2048;
#pragma unroll
        for (int t = 0; t < 8; t++) {
            int i = tid + t * 256;  // 0..2047
            float4 a = s4[2 * i];
            float4 b = s4[2 * i + 1];
            uint4 o;
            o.x = h2(a.x, a.y); o.y = h2(a.z, a.w);
            o.z = h2(b.x, b.y); o.w = h2(b.z, b.w);
            d16[i] = o;
        }
        return;
    }

    const int w = tid >> 5;
    const int lane = tid & 31;
    const int g = lane >> 2;
    const int j = lane & 3;
    const int lr = lane & 7;
    const int grp = lane >> 3;

    const int qt = blockIdx.x;
    const int h = blockIdx.y;
    const int b = blockIdx.z;
    const int q0 = qt * 128;

    const float* qb = q + ((size_t)b * SEQ + q0) * EMB + h * HD;
    const __half* kbp = g_kh + (size_t)b * SEQ * EMB + h * HD;
    const __half* vbp = g_vh + (size_t)b * SEQ * EMB + h * HD;

    const float C = 0.125f * 1.44269504f;

    // ---- stage Q (128x64) fp32 -> fp16 into stage0 directly ----
#pragma unroll
    for (int t = 0; t < 8; t++) {
        int idx = tid + t * 256;
        int row = idx >> 4, c4 = idx & 15;
        float4 val = *reinterpret_cast<const float4*>(qb + (size_t)row * EMB + c4 * 4);
        *reinterpret_cast<uint2*>(dynsm + row * 144 + c4 * 8) =
            make_uint2(h2(val.x, val.y), h2(val.z, val.w));
    }
    __syncthreads();

    unsigned qa[4][4];
#pragma unroll
    for (int kk = 0; kk < 4; kk++) {
        uint32_t addr = smb + (w * 16 + lr + 8 * (grp & 1)) * 144 +
                        kk * 32 + (grp >> 1) * 16;
        ldsm4(qa[kk], addr);
    }
    __syncthreads();

    auto issueKV = [&](int kn, uint32_t st) {
#pragma unroll
        for (int t = 0; t < 2; t++) {
            int c = tid + t * 256;
            int row = c >> 3, col = c & 7;
            cpa16(st + row * 144 + col * 16,
                  kbp + (size_t)(kn * 64 + row) * EMB + col * 8);
            cpa16(st + (64 + row) * 144 + col * 16,
                  vbp + (size_t)(kn * 64 + row) * EMB + col * 8);
        }
        cp_commit();
    };

    issueKV(0, smb);
    issueKV(1, smb + ATTN_STG);

    float oacc[8][4];
#pragma unroll
    for (int n = 0; n < 8; n++)
#pragma unroll
        for (int i = 0; i < 4; i++) oacc[n][i] = 0.f;

    float lp0 = 0.f, lp1 = 0.f;

    const unsigned* mp0 = g_mpack + ((size_t)b * SEQ + q0 + w * 16 + g) * 32;
    const unsigned* mp1 = mp0 + 8 * 32;

    int c3 = 0, i3 = 2;
    for (int kb = 0; kb < 16; kb++) {
        const uint32_t st = smb + c3 * ATTN_STG;
        if (kb < 15) cp_wait1(); else cp_wait0();
        __syncthreads();

        float sacc[8][4];
#pragma unroll
        for (int n = 0; n < 8; n++) {
            sacc[n][0] = sacc[n][1] = sacc[n][2] = sacc[n][3] = 0.f;
            unsigned bk[8];
            uint32_t rb = st + (n * 8 + lr) * 144 + grp * 16;
            ldsm4(bk, rb);
            ldsm4(bk + 4, rb + 64);
#pragma unroll
            for (int kk = 0; kk < 4; kk++) mma_f16(sacc[n], qa[kk], &bk[2 * kk]);
        }

        uint2 w0 = *reinterpret_cast<const uint2*>(mp0 + 2 * kb);
        uint2 w1 = *reinterpret_cast<const uint2*>(mp1 + 2 * kb);
        unsigned long long mm0 = (unsigned long long)w0.x | ((unsigned long long)w0.y << 32);
        unsigned long long mm1 = (unsigned long long)w1.x | ((unsigned long long)w1.y << 32);

#pragma unroll
        for (int n = 0; n < 8; n++) {
            int p = n * 8 + 2 * j;
            float e0 = ((mm0 >> p) & 1) ? ex2(sacc[n][0] * C) : 0.f;
            float e1 = ((mm0 >> (p + 1)) & 1) ? ex2(sacc[n][1] * C) : 0.f;
            float e2 = ((mm1 >> p) & 1) ? ex2(sacc[n][2] * C) : 0.f;
            float e3 = ((mm1 >> (p + 1)) & 1) ? ex2(sacc[n][3] * C) : 0.f;
            sacc[n][0] = e0; sacc[n][1] = e1; sacc[n][2] = e2; sacc[n][3] = e3;
            lp0 += e0 + e1;
            lp1 += e2 + e3;
        }

#pragma unroll
        for (int t = 0; t < 4; t++) {
            unsigned pa[4];
            pa[0] = h2(sacc[2 * t][0], sacc[2 * t][1]);
            pa[1] = h2(sacc[2 * t][2], sacc[2 * t][3]);
            pa[2] = h2(sacc[2 * t + 1][0], sacc[2 * t + 1][1]);
            pa[3] = h2(sacc[2 * t + 1][2], sacc[2 * t + 1][3]);
#pragma unroll
            for (int ndp = 0; ndp < 4; ndp++) {
                unsigned bv[4];
                uint32_t addr = st + (64 + 16 * t + lr + 8 * (grp & 1)) * 144 +
                                ndp * 32 + (grp >> 1) * 16;
                ldsm4t(bv, addr);
                mma_f16(oacc[2 * ndp], pa, bv);
                mma_f16(oacc[2 * ndp + 1], pa, bv + 2);
            }
        }

        if (kb + 2 < 16) issueKV(kb + 2, smb + i3 * ATTN_STG);

        c3 = (c3 == 2) ? 0 : c3 + 1;
        i3 = (i3 == 2) ? 0 : i3 + 1;
    }

    lp0 += __shfl_xor_sync(0xffffffffu, lp0, 1);
    lp0 += __shfl_xor_sync(0xffffffffu, lp0, 2);
    lp1 += __shfl_xor_sync(0xffffffffu, lp1, 1);
    lp1 += __shfl_xor_sync(0xffffffffu, lp1, 2);

    float inv0 = 1.f / lp0, inv1 = 1.f / lp1;
    __half* obase = g_xh + ((size_t)b * SEQ + q0 + w * 16 + g) * EMB + h * HD;
#pragma unroll
    for (int nd = 0; nd < 8; nd++) {
        int col = nd * 8 + 2 * j;
        *reinterpret_cast<unsigned*>(obase + col) =
            h2(oacc[nd][0] * inv0, oacc[nd][1] * inv0);
        *reinterpret_cast<unsigned*>(obase + (size_t)8 * EMB + col) =
            h2(oacc[nd][2] * inv1, oacc[nd][3] * inv1);
    }
}

// ---------------------------------------------------------------------------
// Kernel 3: out = X (4096x1024) @ W^T + b, fp16 mma + ldmatrix,
// K-chunk 64 per stage (2 reg sub-chunks), 3-stage cp.async, 1 barrier/iter.
// ---------------------------------------------------------------------------
#define PROJ_AST 18432
#define PROJ_SMEM (6 * PROJ_AST)

__global__ __launch_bounds__(256, 2) void proj_kernel(
    const float* __restrict__ bias, float* __restrict__ out) {
    extern __shared__ __align__(16) char dynsm[];
    const uint32_t smb = smem_u32(dynsm);

    const int tid = threadIdx.x;
    const int w = tid >> 5, lane = tid & 31, g = lane >> 2, j = lane & 3;
    const int lr = lane & 7, grp = lane >> 3;
    const int wm = (w >> 2) * 64;
    const int wn = (w & 3) * 32;
    const int bm = blockIdx.y * 128;
    const int bn = blockIdx.x * 128;

    const __half* xb = g_xh + (size_t)bm * EMB;
    const __half* wb = g_wh + (size_t)bn * EMB;

    auto issue = [&](int kb, int stg) {
        uint32_t au = smb + stg * PROJ_AST;
        uint32_t bu = smb + 3 * PROJ_AST + stg * PROJ_AST;
#pragma unroll
        for (int t = 0; t < 4; t++) {
            int c = tid + t * 256;
            int row = c >> 3, col = c & 7;
            cpa16(au + row * 144 + col * 16,
                  xb + (size_t)row * EMB + kb * 64 + col * 8);
            cpa16(bu + row * 144 + col * 16,
                  wb + (size_t)row * EMB + kb * 64 + col * 8);
        }
        cp_commit();
    };

    issue(0, 0);
    issue(1, 1);

    float acc[4][4][4];
#pragma unroll
    for (int mi = 0; mi < 4; mi++)
#pragma unroll
        for (int ni = 0; ni < 4; ni++)
#pragma unroll
            for (int i = 0; i < 4; i++) acc[mi][ni][i] = 0.f;

    int c3 = 0, i3 = 2;
    for (int kb = 0; kb < 16; kb++) {
        const uint32_t au = smb + c3 * PROJ_AST;
        const uint32_t bu = smb + 3 * PROJ_AST + c3 * PROJ_AST;
        if (kb < 15) cp_wait1(); else cp_wait0();
        __syncthreads();

#pragma unroll
        for (int half = 0; half < 2; half++) {
            const int cb = half * 64;
            unsigned af[4][2][4];
#pragma unroll
            for (int mi = 0; mi < 4; mi++)
#pragma unroll
                for (int kk = 0; kk < 2; kk++) {
                    uint32_t addr = au + (wm + mi * 16 + lr + 8 * (grp & 1)) * 144 +
                                    cb + kk * 32 + (grp >> 1) * 16;
                    ldsm4(af[mi][kk], addr);
                }
#pragma unroll
            for (int ni = 0; ni < 4; ni++) {
                unsigned bf[4];
                uint32_t addr = bu + (wn + ni * 8 + lr) * 144 + cb + grp * 16;
                ldsm4(bf, addr);
#pragma unroll
                for (int mi = 0; mi < 4; mi++) {
                    mma_f16(acc[mi][ni], af[mi][0], bf);
                    mma_f16(acc[mi][ni], af[mi][1], bf + 2);
                }
            }
        }

        if (kb + 2 < 16) issue(kb + 2, i3);

        c3 = (c3 == 2) ? 0 : c3 + 1;
        i3 = (i3 == 2) ? 0 : i3 + 1;
    }

#pragma unroll
    for (int mi = 0; mi < 4; mi++) {
        int r = bm + wm + mi * 16 + g;
#pragma unroll
        for (int ni = 0; ni < 4; ni++) {
            int col = bn + wn + ni * 8 + 2 * j;
            float2 bb = *reinterpret_cast<const float2*>(bias + col);
            *reinterpret_cast<float2*>(out + (size_t)r * EMB + col) =
                make_float2(acc[mi][ni][0] + bb.x, acc[mi][ni][1] + bb.y);
            *reinterpret_cast<float2*>(out + (size_t)(r + 8) * EMB + col) =
                make_float2(acc[mi][ni][2] + bb.x, acc[mi][ni][3] + bb.y);
        }
    }
}

// ---------------------------------------------------------------------------
extern "C" void kernel_launch(void* const* d_in, const int* in_sizes, int n_in,
                              void* d_out, int out_size) {
    const float* q = (const float*)d_in[0];
    const float* k = (const float*)d_in[1];
    const float* v = (const float*)d_in[2];
    const int* mask = (const int*)d_in[3];
    const float* Wm = (const float*)d_in[4];
    const float* bias = (const float*)d_in[5];
    float* out = (float*)d_out;

    static bool attr_done = false;
    if (!attr_done) {
        cudaFuncSetAttribute(attn_kernel, cudaFuncAttributeMaxDynamicSharedMemorySize,
                             ATTN_SMEM);
        cudaFuncSetAttribute(proj_kernel, cudaFuncAttributeMaxDynamicSharedMemorySize,
                             PROJ_SMEM);
        attr_done = true;
    }

    pre_kernel<<<5120, 256>>>(k, v, mask);

    dim3 ga(9, NH, NB);  // x==8 lane converts W
    attn_kernel<<<ga, 256, ATTN_SMEM>>>(q, Wm);

    dim3 gp(8, 32);
    proj_kernel<<<gp, 256, PROJ_SMEM>>>(bias, out);
}